// round 17
// baseline (speedup 1.0000x reference)
#include <cuda_runtime.h>
#include <cuda_bf16.h>
#include <cstdint>

// GrahamLoss: single fused kernel. S=bf16(F+D), T=bf16(D-F) are produced
// on-demand by work-stealing (128 units = 16 batches x 8 row-blocks; first
// CTA to need a unit claims+converts it once, others spin on done flag),
// overlapping conversion with MMA work chip-wide.
// Then per 64x64 pair-tile (I<=J, 8x8 grid, x16 batches = 576 CTAs):
// split-K warp-pairs compute P=S_I T_J^T, Q=S_J T_I^T (32x64 warp tiles,
// diag: 4-way split-K on P), pair P with Q^T in smem, square, weight,
// reduce; last CTA finalizes and resets all flags for graph replay.

#define B_    16
#define C_    512
#define HW_   1024
#define NELT  ((size_t)B_ * C_ * HW_)   // 8388608
#define KC    64             // bf16 k per chunk
#define NCH   (HW_ / KC)     // 16
#define NT2   36
#define NPART (B_ * NT2)     // 576
#define NUNIT 128            // 16 batches x 8 row-blocks

// smem: 3 stages x 32KB (4 panels x 8KB: 64 rows x 128B swizzled)
#define OSI 0
#define OTI 8192
#define OSJ 16384
#define OTJ 24576
#define STG 32768
#define DYN_SMEM (3 * STG)   // 96 KB
#define EPW 65               // epilogue buffer row stride (floats)

__device__ __align__(16) __nv_bfloat16 g_S[NELT];   // 16.7 MB
__device__ __align__(16) __nv_bfloat16 g_T[NELT];   // 16.7 MB
__device__ float        g_partials[NPART];
__device__ unsigned int g_count;
__device__ unsigned int g_claim[NUNIT];   // zero-init; reset by last CTA
__device__ unsigned int g_done[NUNIT];

__constant__ int c_u[NT2] = {0,0,0,0,0,0,0,0,1,1,1,1,1,1,1,2,2,2,2,2,2,3,3,3,3,3,4,4,4,4,5,5,5,6,6,7};
__constant__ int c_v[NT2] = {0,1,2,3,4,5,6,7,1,2,3,4,5,6,7,2,3,4,5,6,7,3,4,5,6,7,4,5,6,7,5,6,7,6,7,7};

// ---------- helpers ----------
__device__ __forceinline__ uint32_t smem_u32(const void* p) {
    uint32_t a;
    asm("{ .reg .u64 t; cvta.to.shared.u64 t, %1; cvt.u32.u64 %0, t; }" : "=r"(a) : "l"(p));
    return a;
}
__device__ __forceinline__ uint32_t paddr(uint32_t pbase, int row, int k) {
    return pbase + (uint32_t)row * 128u
         + ((((uint32_t)(k >> 3) ^ (uint32_t)row) & 7u) << 4) + ((uint32_t)(k & 7) << 1);
}
__device__ __forceinline__ uint32_t pack2(float hi, float lo) {
    uint32_t r;
    asm("cvt.rn.bf16x2.f32 %0, %1, %2;" : "=r"(r) : "f"(hi), "f"(lo));
    return r;
}
__device__ __forceinline__ void cp_async16(uint32_t dst, const void* src) {
    asm volatile("cp.async.cg.shared.global [%0], [%1], 16;" :: "r"(dst), "l"(src) : "memory");
}
__device__ __forceinline__ void cp_commit() { asm volatile("cp.async.commit_group;" ::: "memory"); }
template <int N>
__device__ __forceinline__ void cp_wait() { asm volatile("cp.async.wait_group %0;" :: "n"(N) : "memory"); }
__device__ __forceinline__ void ldm_x4(uint32_t* r, uint32_t addr) {
    asm volatile("ldmatrix.sync.aligned.m8n8.x4.shared.b16 {%0,%1,%2,%3}, [%4];"
                 : "=r"(r[0]), "=r"(r[1]), "=r"(r[2]), "=r"(r[3]) : "r"(addr));
}
__device__ __forceinline__ void mma_bf16(float* d, const uint32_t* a, const uint32_t* b) {
    asm volatile("mma.sync.aligned.m16n8k16.row.col.f32.bf16.bf16.f32 "
                 "{%0,%1,%2,%3}, {%4,%5,%6,%7}, {%8,%9}, {%0,%1,%2,%3};"
                 : "+f"(d[0]), "+f"(d[1]), "+f"(d[2]), "+f"(d[3])
                 : "r"(a[0]), "r"(a[1]), "r"(a[2]), "r"(a[3]), "r"(b[0]), "r"(b[1]));
}

struct Frag { uint32_t a[2][4]; uint32_t b[8][2]; };   // 32x64 warp tile, one k16

__device__ __forceinline__ void ld_fr(uint32_t pA, int arow0, uint32_t pB,
                                      int k0, int lane, Frag& f) {
    const int a_row = lane & 15;
    const int a_k   = (lane >> 4) << 3;
    ldm_x4(f.a[0], paddr(pA, arow0 + a_row,      k0 + a_k));
    ldm_x4(f.a[1], paddr(pA, arow0 + 16 + a_row, k0 + a_k));
    const int b_row = (((lane >> 4) & 1) << 3) + (lane & 7);
    const int b_k   = ((lane >> 3) & 1) << 3;
    #pragma unroll
    for (int tp = 0; tp < 4; tp++) {
        uint32_t t4[4];
        ldm_x4(t4, paddr(pB, tp * 16 + b_row, k0 + b_k));
        f.b[2 * tp][0] = t4[0]; f.b[2 * tp][1] = t4[1];
        f.b[2 * tp + 1][0] = t4[2]; f.b[2 * tp + 1][1] = t4[3];
    }
}
__device__ __forceinline__ void mma_fr(float acc[2][8][4], const Frag& f) {
    #pragma unroll
    for (int mt = 0; mt < 2; mt++)
        #pragma unroll
        for (int nt = 0; nt < 8; nt++)
            mma_bf16(acc[mt][nt], f.a[mt], f.b[nt]);
}

// convert one 64-row unit u (batch u>>3, block u&7): fp32 F,D -> bf16 S,T
__device__ void convert_unit(int u, const float* __restrict__ F,
                             const float* __restrict__ Dm, int tid) {
    const size_t base4 = ((size_t)(u >> 3) * C_ + (u & 7) * 64) * (HW_ / 4);  // float4 idx
    const float4* F4 = (const float4*)F + base4;
    const float4* D4 = (const float4*)Dm + base4;
    uint2* S2 = (uint2*)g_S + base4;
    uint2* T2 = (uint2*)g_T + base4;
    #pragma unroll 4
    for (int j = 0; j < 64; j++) {
        int i = tid + j * 256;                 // 16384 float4 slots
        float4 f = F4[i];
        float4 d = D4[i];
        S2[i] = make_uint2(pack2(f.y + d.y, f.x + d.x), pack2(f.w + d.w, f.z + d.z));
        T2[i] = make_uint2(pack2(d.y - f.y, d.x - f.x), pack2(d.w - f.w, d.z - f.z));
    }
}

// ---------- fused kernel ----------
__global__ __launch_bounds__(256, 2)
void gram_fused_kernel(const float* __restrict__ F, const float* __restrict__ Dm,
                       float* __restrict__ out) {
    extern __shared__ __align__(128) unsigned char smem[];
    __shared__ float red[256];
    __shared__ unsigned int s_islast;
    __shared__ int s_won[2];

    const int tid  = threadIdx.x;
    const int lane = tid & 31;
    const int wid  = tid >> 5;
    const int b    = blockIdx.y;
    const int I = c_u[blockIdx.x];
    const int J = c_v[blockIdx.x];
    const int diag = (I == J);
    const float w = diag ? 1.0f : 2.0f;

    // ---- phase 0: work-stealing S/T conversion ----
    const int uI = b * 8 + I;
    const int uJ = b * 8 + J;
    if (tid == 0) {
        s_won[0] = (atomicCAS(&g_claim[uI], 0u, 1u) == 0u);
        s_won[1] = (!diag) && (atomicCAS(&g_claim[uJ], 0u, 1u) == 0u);
    }
    __syncthreads();
    if (s_won[0]) {
        convert_unit(uI, F, Dm, tid);
        __syncthreads();
        if (tid == 0) { __threadfence(); atomicExch(&g_done[uI], 1u); }
    }
    if (s_won[1]) {
        convert_unit(uJ, F, Dm, tid);
        __syncthreads();
        if (tid == 0) { __threadfence(); atomicExch(&g_done[uJ], 1u); }
    }
    if (tid == 0) {
        while (atomicAdd(&g_done[uI], 0u) == 0u) __nanosleep(64);
        if (!diag) while (atomicAdd(&g_done[uJ], 0u) == 0u) __nanosleep(64);
        __threadfence();
    }
    __syncthreads();

    // ---- phase 1: gram mainloop (R14 body) ----
    const __nv_bfloat16* SIg = g_S + ((size_t)b * C_ + I * 64) * HW_;
    const __nv_bfloat16* TIg = g_T + ((size_t)b * C_ + I * 64) * HW_;
    const __nv_bfloat16* SJg = g_S + ((size_t)b * C_ + J * 64) * HW_;
    const __nv_bfloat16* TJg = g_T + ((size_t)b * C_ + J * 64) * HW_;

    const uint32_t sbase = smem_u32(smem);

    const int bufid = wid >> 1;
    const int arow0 = (wid & 1) * 32;
    uint32_t oA, oB;
    int ks0, nks;
    if (diag) { oA = OSI; oB = OTI; ks0 = bufid; nks = 1; }
    else {
        int role = bufid & 1, kg = bufid >> 1;
        oA = role ? OSJ : OSI;
        oB = role ? OTI : OTJ;
        ks0 = kg * 2; nks = 2;
    }
    const int k0a = ks0 * 16;
    const int k0b = (ks0 + 1) * 16;

    const int prow = tid >> 3;
    const int pu   = tid & 7;
    const uint32_t pso = (uint32_t)prow * 128u + ((((uint32_t)pu ^ (uint32_t)prow) & 7u) << 4);
    const uint32_t pso2 = (uint32_t)(prow + 32) * 128u
                        + ((((uint32_t)pu ^ (uint32_t)(prow + 32)) & 7u) << 4);
    const size_t pgb  = (size_t)prow * HW_ + pu * 8;
    const size_t pgb2 = (size_t)(prow + 32) * HW_ + pu * 8;

    auto issue = [&](int c) {
        const uint32_t stg = sbase + (uint32_t)(c % 3) * STG;
        const int kb = c * KC;
        cp_async16(stg + OSI + pso,  SIg + pgb  + kb);
        cp_async16(stg + OTI + pso,  TIg + pgb  + kb);
        cp_async16(stg + OSI + pso2, SIg + pgb2 + kb);
        cp_async16(stg + OTI + pso2, TIg + pgb2 + kb);
        if (!diag) {
            cp_async16(stg + OSJ + pso,  SJg + pgb  + kb);
            cp_async16(stg + OTJ + pso,  TJg + pgb  + kb);
            cp_async16(stg + OSJ + pso2, SJg + pgb2 + kb);
            cp_async16(stg + OTJ + pso2, TJg + pgb2 + kb);
        }
        cp_commit();
    };

    float acc[2][8][4];
    #pragma unroll
    for (int mt = 0; mt < 2; mt++)
        #pragma unroll
        for (int nt = 0; nt < 8; nt++)
            #pragma unroll
            for (int r = 0; r < 4; r++) acc[mt][nt][r] = 0.f;

    issue(0);
    issue(1);

    for (int c = 0; c < NCH; c++) {
        if (c == NCH - 1) cp_wait<0>(); else cp_wait<1>();
        __syncthreads();
        if (c + 2 < NCH) issue(c + 2);

        const uint32_t stb = sbase + (uint32_t)(c % 3) * STG;
        const uint32_t pA = stb + oA;
        const uint32_t pB = stb + oB;

        Frag f0;
        ld_fr(pA, arow0, pB, k0a, lane, f0);
        if (nks == 2) {
            Frag f1;
            ld_fr(pA, arow0, pB, k0b, lane, f1);
            mma_fr(acc, f0);
            mma_fr(acc, f1);
        } else {
            mma_fr(acc, f0);
        }
    }
    __syncthreads();   // all stage reads done; smem reusable

    // ---- epilogue: 4 partial buffers, pair P with Q^T ----
    float* sBuf = (float*)smem;                 // 4 x (64 x EPW) = 66560 B
    {
        float* dst = sBuf + bufid * (64 * EPW);
        const int quad = lane >> 2;
        const int tcol = (lane & 3) * 2;
        #pragma unroll
        for (int mt = 0; mt < 2; mt++) {
            #pragma unroll
            for (int nt = 0; nt < 8; nt++) {
                int r0 = arow0 + mt * 16 + quad;
                int c0 = nt * 8 + tcol;
                dst[r0 * EPW + c0]             = acc[mt][nt][0];
                dst[r0 * EPW + c0 + 1]         = acc[mt][nt][1];
                dst[(r0 + 8) * EPW + c0]       = acc[mt][nt][2];
                dst[(r0 + 8) * EPW + c0 + 1]   = acc[mt][nt][3];
            }
        }
    }
    __syncthreads();

    const float* B0 = sBuf;
    const float* B1 = sBuf + 1 * (64 * EPW);
    const float* B2 = sBuf + 2 * (64 * EPW);
    const float* B3 = sBuf + 3 * (64 * EPW);
    float local = 0.f;
    #pragma unroll
    for (int i = 0; i < 16; i++) {
        int e = tid + i * 256;
        int r = e >> 6, cc = e & 63;
        float p, q;
        if (diag) {
            p = (B0[r * EPW + cc] + B1[r * EPW + cc]) + (B2[r * EPW + cc] + B3[r * EPW + cc]);
            q = (B0[cc * EPW + r] + B1[cc * EPW + r]) + (B2[cc * EPW + r] + B3[cc * EPW + r]);
        } else {
            p = B0[r * EPW + cc] + B2[r * EPW + cc];
            q = B1[cc * EPW + r] + B3[cc * EPW + r];
        }
        float val = 0.5f * (p + q);
        local = fmaf(val, val, local);
    }
    local *= w;

    red[tid] = local;
    __syncthreads();
    #pragma unroll
    for (int stp = 128; stp > 0; stp >>= 1) {
        if (tid < stp) red[tid] += red[tid + stp];
        __syncthreads();
    }

    if (tid == 0) {
        g_partials[b * NT2 + blockIdx.x] = red[0];
        __threadfence();
        unsigned int prev = atomicAdd(&g_count, 1u);
        s_islast = (prev == NPART - 1) ? 1u : 0u;
    }
    __syncthreads();
    if (s_islast) {
        __threadfence();
        float v = 0.f;
        for (int i = tid; i < NPART; i += 256) v += g_partials[i];
        red[tid] = v;
        __syncthreads();
        #pragma unroll
        for (int stp = 128; stp > 0; stp >>= 1) {
            if (tid < stp) red[tid] += red[tid + stp];
            __syncthreads();
        }
        // reset flags for next graph replay (all CTAs are past conversion)
        if (tid < NUNIT) { g_claim[tid] = 0u; g_done[tid] = 0u; }
        if (tid == 0) {
            out[0] = red[0] * (1.0f / 1099511627776.0f);  // / 2^40
            g_count = 0;
        }
    }
}

extern "C" void kernel_launch(void* const* d_in, const int* in_sizes, int n_in,
                              void* d_out, int out_size) {
    const float* F = (const float*)d_in[0];   // feat
    const float* D = (const float*)d_in[1];   // feat_decod
    float* out = (float*)d_out;

    cudaFuncSetAttribute(gram_fused_kernel, cudaFuncAttributeMaxDynamicSharedMemorySize, DYN_SMEM);
    dim3 grid(NT2, B_);
    gram_fused_kernel<<<grid, 256, DYN_SMEM>>>(F, D, out);
}